// round 1
// baseline (speedup 1.0000x reference)
#include <cuda_runtime.h>

#define N_NODES 65536
#define N_EDGES 1048576
#define HID 80
#define NCH 48   // 32 scalar channels + 16 vector channels, one float4 each

// ---------------- static scratch (no allocations allowed) ----------------
__device__ float  g_h0[N_NODES * HID];
__device__ float  g_h1[N_NODES * HID];
__device__ float4 g_V[N_NODES * NCH];
__device__ int    g_deg[N_NODES];
__device__ int    g_rowptr[N_NODES + 1];
__device__ int    g_cursor[N_NODES];
__device__ int    g_csrc[N_EDGES];
__device__ float4 g_coef[N_EDGES];

// normalization constants (e3nn fan-in norms * 1/sqrt(2) * 1/sqrt(DEG=16))
// K1 = (1/sqrt2)/sqrt(32)/4 = 1/32
// K2 = (1/sqrt2)/sqrt(48)/4 = 1/(16*sqrt6)
// K3 = K1
// K4 = (1/sqrt2)/sqrt(16)/4 = 1/(16*sqrt2)
#define K1C (0.03125f)
#define K2C (0.025515518f)
#define K3C (0.03125f)
#define K4C (0.044194174f)

// ---------------- preprocessing ----------------
__global__ void k_zero(int* __restrict__ deg) {
    int i = blockIdx.x * blockDim.x + threadIdx.x;
    if (i < N_NODES) deg[i] = 0;
}

__global__ void k_hist(const int* __restrict__ dst, int* __restrict__ deg) {
    int e = blockIdx.x * blockDim.x + threadIdx.x;
    if (e < N_EDGES) atomicAdd(&deg[dst[e]], 1);
}

// single-block exclusive scan over 65536 ints (256 threads x 256 elems)
__global__ void k_scan(const int* __restrict__ deg, int* __restrict__ rowptr,
                       int* __restrict__ cursor) {
    __shared__ int sums[256];
    int tid = threadIdx.x;
    int base = tid * 256;
    int s = 0;
    for (int i = 0; i < 256; i++) s += deg[base + i];
    sums[tid] = s;
    __syncthreads();
    if (tid == 0) {
        int acc = 0;
        for (int i = 0; i < 256; i++) { int t = sums[i]; sums[i] = acc; acc += t; }
    }
    __syncthreads();
    int off = sums[tid];
    for (int i = 0; i < 256; i++) {
        rowptr[base + i] = off;
        cursor[base + i] = off;
        off += deg[base + i];
    }
    if (tid == 255) rowptr[N_NODES] = off;
}

__global__ void k_csr(const int* __restrict__ src, const int* __restrict__ dst,
                      const float4* __restrict__ eattr,
                      int* __restrict__ cursor, int* __restrict__ csrc,
                      float4* __restrict__ coef) {
    int e = blockIdx.x * blockDim.x + threadIdx.x;
    if (e >= N_EDGES) return;
    int d = dst[e];
    int pos = atomicAdd(&cursor[d], 1);
    csrc[pos] = src[e];
    coef[pos] = eattr[e];   // (s2, v2x, v2y, v2z)
}

// ---------------- input embed: h = x @ W_in + b_in ----------------
__global__ void k_input(const float* __restrict__ x, const float* __restrict__ W_in,
                        const float* __restrict__ b_in, float* __restrict__ h) {
    int id = blockIdx.x * blockDim.x + threadIdx.x;   // N*80
    if (id >= N_NODES * HID) return;
    int n = id / HID, c = id % HID;
    const float* xr = x + n * 16;
    float acc = b_in[c];
#pragma unroll
    for (int i = 0; i < 16; i++) acc = fmaf(xr[i], W_in[i * HID + c], acc);
    h[id] = acc;
}

// ---------------- per-node transform: build V (48 float4 per node) ----------------
// ch in [0,32):  (P1[ch], T2[ch,0], T2[ch,1], T2[ch,2])
// ch in [32,48): c=ch-32 -> (P3[c], T4[c,0], T4[c,1], T4[c,2])
__global__ void k_node(const float* __restrict__ h,
                       const float* __restrict__ w1, const float* __restrict__ w2,
                       const float* __restrict__ w3, const float* __restrict__ w4,
                       float4* __restrict__ V) {
    int id = blockIdx.x * blockDim.x + threadIdx.x;   // N*48
    if (id >= N_NODES * NCH) return;
    int n = id / NCH, ch = id % NCH;
    const float* hn = h + n * HID;
    float p = 0.f, t0 = 0.f, t1 = 0.f, t2 = 0.f;
    if (ch < 32) {
#pragma unroll
        for (int a = 0; a < 32; a++) p = fmaf(hn[a], w1[a * 32 + ch], p);
#pragma unroll
        for (int a = 0; a < 16; a++) {
            float wa = w2[a * 32 + ch];
            t0 = fmaf(hn[32 + a * 3 + 0], wa, t0);
            t1 = fmaf(hn[32 + a * 3 + 1], wa, t1);
            t2 = fmaf(hn[32 + a * 3 + 2], wa, t2);
        }
        V[id] = make_float4(K1C * p, K2C * t0, K2C * t1, K2C * t2);
    } else {
        int c = ch - 32;
#pragma unroll
        for (int a = 0; a < 32; a++) p = fmaf(hn[a], w3[a * 16 + c], p);
#pragma unroll
        for (int a = 0; a < 16; a++) {
            float wa = w4[a * 16 + c];
            t0 = fmaf(hn[32 + a * 3 + 0], wa, t0);
            t1 = fmaf(hn[32 + a * 3 + 1], wa, t1);
            t2 = fmaf(hn[32 + a * 3 + 2], wa, t2);
        }
        V[id] = make_float4(K3C * p, K4C * t0, K4C * t1, K4C * t2);
    }
}

// ---------------- aggregation: per (dst node, channel) ----------------
__global__ void k_agg(const float4* __restrict__ V, const int* __restrict__ rowptr,
                      const int* __restrict__ csrc, const float4* __restrict__ coef,
                      float* __restrict__ hout) {
    int id = blockIdx.x * blockDim.x + threadIdx.x;   // N*48
    if (id >= N_NODES * NCH) return;
    int n = id / NCH, ch = id % NCH;
    int beg = rowptr[n], end = rowptr[n + 1];
    float a0 = 0.f, a1 = 0.f, a2 = 0.f;
    bool is_s = (ch < 32);
    for (int e = beg; e < end; e++) {
        int s = csrc[e];
        float4 cf = coef[e];               // broadcast within warp
        float4 v = V[s * NCH + ch];        // coalesced across channels
        if (is_s) {
            a0 = fmaf(cf.x, v.x, a0);
            a0 = fmaf(cf.y, v.y, a0);
            a0 = fmaf(cf.z, v.z, a0);
            a0 = fmaf(cf.w, v.w, a0);
        } else {
            a0 = fmaf(cf.y, v.x, fmaf(cf.x, v.y, a0));
            a1 = fmaf(cf.z, v.x, fmaf(cf.x, v.z, a1));
            a2 = fmaf(cf.w, v.x, fmaf(cf.x, v.w, a2));
        }
    }
    if (is_s) {
        hout[n * HID + ch] = a0;
    } else {
        int b = n * HID + 32 + (ch - 32) * 3;
        hout[b + 0] = a0;
        hout[b + 1] = a1;
        hout[b + 2] = a2;
    }
}

// ---------------- readout: relu(h) @ W_out + b_out ----------------
__global__ void k_out(const float* __restrict__ h, const float* __restrict__ W_out,
                      const float* __restrict__ b_out, float* __restrict__ out) {
    int id = blockIdx.x * blockDim.x + threadIdx.x;   // N*8
    if (id >= N_NODES * 8) return;
    int n = id / 8, o = id % 8;
    const float* hn = h + n * HID;
    float acc = b_out[o];
#pragma unroll
    for (int c = 0; c < HID; c++)
        acc = fmaf(fmaxf(hn[c], 0.f), W_out[c * 8 + o], acc);
    out[id] = acc;
}

// ---------------- launch ----------------
extern "C" void kernel_launch(void* const* d_in, const int* in_sizes, int n_in,
                              void* d_out, int out_size) {
    const float* x     = (const float*)d_in[0];
    const int*   eidx  = (const int*)d_in[1];     // (2, E) int32: row0=src, row1=dst
    const float* eattr = (const float*)d_in[2];   // (E, 4)
    const float* W_in  = (const float*)d_in[3];
    const float* b_in  = (const float*)d_in[4];
    const float* tpw1  = (const float*)d_in[5];   // (3,32,32)
    const float* tpw2  = (const float*)d_in[6];   // (3,16,32)
    const float* tpw3  = (const float*)d_in[7];   // (3,32,16)
    const float* tpw4  = (const float*)d_in[8];   // (3,16,16)
    const float* W_out = (const float*)d_in[9];
    const float* b_out = (const float*)d_in[10];
    float* out = (float*)d_out;

    float *h0, *h1; float4 *V, *coef; int *deg, *rowptr, *cursor, *csrc;
    cudaGetSymbolAddress((void**)&h0,     g_h0);
    cudaGetSymbolAddress((void**)&h1,     g_h1);
    cudaGetSymbolAddress((void**)&V,      g_V);
    cudaGetSymbolAddress((void**)&deg,    g_deg);
    cudaGetSymbolAddress((void**)&rowptr, g_rowptr);
    cudaGetSymbolAddress((void**)&cursor, g_cursor);
    cudaGetSymbolAddress((void**)&csrc,   g_csrc);
    cudaGetSymbolAddress((void**)&coef,   g_coef);

    const int* src = eidx;
    const int* dst = eidx + N_EDGES;

    // CSR build (once per launch; amortized over 3 layers)
    k_zero<<<N_NODES / 256, 256>>>(deg);
    k_hist<<<N_EDGES / 256, 256>>>(dst, deg);
    k_scan<<<1, 256>>>(deg, rowptr, cursor);
    k_csr<<<N_EDGES / 256, 256>>>(src, dst, (const float4*)eattr, cursor, csrc, coef);

    // input embed
    k_input<<<(N_NODES * HID) / 256, 256>>>(x, W_in, b_in, h0);

    float* hc = h0;
    float* hn = h1;
    for (int l = 0; l < 3; l++) {
        k_node<<<(N_NODES * NCH) / 256, 256>>>(hc,
            tpw1 + l * 32 * 32, tpw2 + l * 16 * 32,
            tpw3 + l * 32 * 16, tpw4 + l * 16 * 16, V);
        k_agg<<<(N_NODES * NCH) / 256, 256>>>(V, rowptr, csrc, coef, hn);
        float* t = hc; hc = hn; hn = t;
    }

    // readout
    k_out<<<(N_NODES * 8) / 256, 256>>>(hc, W_out, b_out, out);
}

// round 2
// speedup vs baseline: 1.0350x; 1.0350x over previous
#include <cuda_runtime.h>

#define N_NODES 65536
#define N_EDGES 1048576
#define HID 80
#define NCH 48   // 32 scalar channels + 16 vector channels, one float4 each
#define EDGE_CHUNK 64

// ---------------- static scratch (no allocations allowed) ----------------
__device__ float  g_h0[N_NODES * HID];
__device__ float  g_h1[N_NODES * HID];
__device__ float4 g_V[N_NODES * NCH];
__device__ int    g_deg[N_NODES];
__device__ int    g_rowptr[N_NODES + 1];
__device__ int    g_cursor[N_NODES];
__device__ int    g_csrc[N_EDGES];
__device__ float4 g_coef[N_EDGES];

// normalization constants (e3nn fan-in norms * 1/sqrt(2) * 1/sqrt(DEG=16))
#define K1C (0.03125f)
#define K2C (0.025515518f)
#define K3C (0.03125f)
#define K4C (0.044194174f)

// ---------------- preprocessing ----------------
__global__ void k_zero(int* __restrict__ deg) {
    int i = blockIdx.x * blockDim.x + threadIdx.x;
    if (i < N_NODES) deg[i] = 0;
}

__global__ void k_hist(const int* __restrict__ dst, int* __restrict__ deg) {
    int e = blockIdx.x * blockDim.x + threadIdx.x;
    if (e < N_EDGES) atomicAdd(&deg[dst[e]], 1);
}

// single-block exclusive scan over 65536 ints (256 threads x 256 elems)
__global__ void k_scan(const int* __restrict__ deg, int* __restrict__ rowptr,
                       int* __restrict__ cursor) {
    __shared__ int sums[256];
    int tid = threadIdx.x;
    int base = tid * 256;
    int s = 0;
#pragma unroll 8
    for (int i = 0; i < 256; i++) s += deg[base + i];
    sums[tid] = s;
    __syncthreads();
    if (tid == 0) {
        int acc = 0;
        for (int i = 0; i < 256; i++) { int t = sums[i]; sums[i] = acc; acc += t; }
    }
    __syncthreads();
    int off = sums[tid];
    for (int i = 0; i < 256; i++) {
        rowptr[base + i] = off;
        cursor[base + i] = off;
        off += deg[base + i];
    }
    if (tid == 255) rowptr[N_NODES] = off;
}

__global__ void k_csr(const int* __restrict__ src, const int* __restrict__ dst,
                      const float4* __restrict__ eattr,
                      int* __restrict__ cursor, int* __restrict__ csrc,
                      float4* __restrict__ coef) {
    int e = blockIdx.x * blockDim.x + threadIdx.x;
    if (e >= N_EDGES) return;
    int d = dst[e];
    int pos = atomicAdd(&cursor[d], 1);
    csrc[pos] = src[e];
    coef[pos] = eattr[e];   // (s2, v2x, v2y, v2z)
}

// ---------------- input embed: h = x @ W_in + b_in ----------------
__global__ void k_input(const float* __restrict__ x, const float* __restrict__ W_in,
                        const float* __restrict__ b_in, float* __restrict__ h) {
    int id = blockIdx.x * blockDim.x + threadIdx.x;   // N*80
    if (id >= N_NODES * HID) return;
    int n = id / HID, c = id % HID;
    const float* xr = x + n * 16;
    float acc = b_in[c];
#pragma unroll
    for (int i = 0; i < 16; i++) acc = fmaf(xr[i], W_in[i * HID + c], acc);
    h[id] = acc;
}

// ---------------- per-node transform: build V (48 float4 per node) ----------------
__global__ void k_node(const float* __restrict__ h,
                       const float* __restrict__ w1, const float* __restrict__ w2,
                       const float* __restrict__ w3, const float* __restrict__ w4,
                       float4* __restrict__ V) {
    int id = blockIdx.x * blockDim.x + threadIdx.x;   // N*48
    if (id >= N_NODES * NCH) return;
    int n = id / NCH, ch = id % NCH;
    const float* hn = h + n * HID;
    float p = 0.f, t0 = 0.f, t1 = 0.f, t2 = 0.f;
    if (ch < 32) {
#pragma unroll
        for (int a = 0; a < 32; a++) p = fmaf(hn[a], w1[a * 32 + ch], p);
#pragma unroll
        for (int a = 0; a < 16; a++) {
            float wa = w2[a * 32 + ch];
            t0 = fmaf(hn[32 + a * 3 + 0], wa, t0);
            t1 = fmaf(hn[32 + a * 3 + 1], wa, t1);
            t2 = fmaf(hn[32 + a * 3 + 2], wa, t2);
        }
        V[id] = make_float4(K1C * p, K2C * t0, K2C * t1, K2C * t2);
    } else {
        int c = ch - 32;
#pragma unroll
        for (int a = 0; a < 32; a++) p = fmaf(hn[a], w3[a * 16 + c], p);
#pragma unroll
        for (int a = 0; a < 16; a++) {
            float wa = w4[a * 16 + c];
            t0 = fmaf(hn[32 + a * 3 + 0], wa, t0);
            t1 = fmaf(hn[32 + a * 3 + 1], wa, t1);
            t2 = fmaf(hn[32 + a * 3 + 2], wa, t2);
        }
        V[id] = make_float4(K3C * p, K4C * t0, K4C * t1, K4C * t2);
    }
}

// ---------------- aggregation: one block (64 threads) per dst node ----------------
// Threads 0..47 each own a channel; edge metadata staged in smem once per node.
__device__ __forceinline__ void agg_node(
    const float4* __restrict__ V, const int* __restrict__ rowptr,
    const int* __restrict__ csrc, const float4* __restrict__ coef,
    int n, int tid, int* s_src, float4* s_cf,
    float& a0, float& a1, float& a2)
{
    int beg = rowptr[n], end = rowptr[n + 1];
    int ch = tid;
    bool is_s = (ch < 32);
    a0 = a1 = a2 = 0.f;
    for (int base = beg; base < end; base += EDGE_CHUNK) {
        int cnt = min(EDGE_CHUNK, end - base);
        __syncthreads();
        if (tid < cnt) {
            s_src[tid] = csrc[base + tid];
            s_cf[tid]  = coef[base + tid];
        }
        __syncthreads();
        if (ch < NCH) {
#pragma unroll 4
            for (int i = 0; i < cnt; i++) {
                int s = s_src[i];
                float4 cf = s_cf[i];
                float4 v = V[s * NCH + ch];
                if (is_s) {
                    a0 = fmaf(cf.x, v.x, a0);
                    a0 = fmaf(cf.y, v.y, a0);
                    a0 = fmaf(cf.z, v.z, a0);
                    a0 = fmaf(cf.w, v.w, a0);
                } else {
                    a0 = fmaf(cf.y, v.x, fmaf(cf.x, v.y, a0));
                    a1 = fmaf(cf.z, v.x, fmaf(cf.x, v.z, a1));
                    a2 = fmaf(cf.w, v.x, fmaf(cf.x, v.w, a2));
                }
            }
        }
    }
}

__global__ __launch_bounds__(64) void k_agg(
    const float4* __restrict__ V, const int* __restrict__ rowptr,
    const int* __restrict__ csrc, const float4* __restrict__ coef,
    float* __restrict__ hout)
{
    __shared__ int    s_src[EDGE_CHUNK];
    __shared__ float4 s_cf[EDGE_CHUNK];
    int n = blockIdx.x;
    int tid = threadIdx.x;
    float a0, a1, a2;
    agg_node(V, rowptr, csrc, coef, n, tid, s_src, s_cf, a0, a1, a2);
    if (tid < 32) {
        hout[n * HID + tid] = a0;
    } else if (tid < NCH) {
        int b = n * HID + 32 + (tid - 32) * 3;
        hout[b + 0] = a0;
        hout[b + 1] = a1;
        hout[b + 2] = a2;
    }
}

// last layer: fuse ReLU + W_out readout (node vector already block-resident)
__global__ __launch_bounds__(64) void k_agg_final(
    const float4* __restrict__ V, const int* __restrict__ rowptr,
    const int* __restrict__ csrc, const float4* __restrict__ coef,
    const float* __restrict__ W_out, const float* __restrict__ b_out,
    float* __restrict__ out)
{
    __shared__ int    s_src[EDGE_CHUNK];
    __shared__ float4 s_cf[EDGE_CHUNK];
    __shared__ float  sh[HID];
    int n = blockIdx.x;
    int tid = threadIdx.x;
    float a0, a1, a2;
    agg_node(V, rowptr, csrc, coef, n, tid, s_src, s_cf, a0, a1, a2);
    __syncthreads();
    if (tid < 32) {
        sh[tid] = fmaxf(a0, 0.f);
    } else if (tid < NCH) {
        int b = 32 + (tid - 32) * 3;
        sh[b + 0] = fmaxf(a0, 0.f);
        sh[b + 1] = fmaxf(a1, 0.f);
        sh[b + 2] = fmaxf(a2, 0.f);
    }
    __syncthreads();
    if (tid < 8) {
        float acc = b_out[tid];
#pragma unroll
        for (int c = 0; c < HID; c++)
            acc = fmaf(sh[c], W_out[c * 8 + tid], acc);
        out[n * 8 + tid] = acc;
    }
}

// ---------------- launch ----------------
extern "C" void kernel_launch(void* const* d_in, const int* in_sizes, int n_in,
                              void* d_out, int out_size) {
    const float* x     = (const float*)d_in[0];
    const int*   eidx  = (const int*)d_in[1];     // (2, E) int32: row0=src, row1=dst
    const float* eattr = (const float*)d_in[2];   // (E, 4)
    const float* W_in  = (const float*)d_in[3];
    const float* b_in  = (const float*)d_in[4];
    const float* tpw1  = (const float*)d_in[5];   // (3,32,32)
    const float* tpw2  = (const float*)d_in[6];   // (3,16,32)
    const float* tpw3  = (const float*)d_in[7];   // (3,32,16)
    const float* tpw4  = (const float*)d_in[8];   // (3,16,16)
    const float* W_out = (const float*)d_in[9];
    const float* b_out = (const float*)d_in[10];
    float* out = (float*)d_out;

    float *h0, *h1; float4 *V, *coef; int *deg, *rowptr, *cursor, *csrc;
    cudaGetSymbolAddress((void**)&h0,     g_h0);
    cudaGetSymbolAddress((void**)&h1,     g_h1);
    cudaGetSymbolAddress((void**)&V,      g_V);
    cudaGetSymbolAddress((void**)&deg,    g_deg);
    cudaGetSymbolAddress((void**)&rowptr, g_rowptr);
    cudaGetSymbolAddress((void**)&cursor, g_cursor);
    cudaGetSymbolAddress((void**)&csrc,   g_csrc);
    cudaGetSymbolAddress((void**)&coef,   g_coef);

    const int* src = eidx;
    const int* dst = eidx + N_EDGES;

    // CSR build
    k_zero<<<N_NODES / 256, 256>>>(deg);
    k_hist<<<N_EDGES / 256, 256>>>(dst, deg);
    k_scan<<<1, 256>>>(deg, rowptr, cursor);
    k_csr<<<N_EDGES / 256, 256>>>(src, dst, (const float4*)eattr, cursor, csrc, coef);

    // input embed
    k_input<<<(N_NODES * HID) / 256, 256>>>(x, W_in, b_in, h0);

    // layers 0,1: node transform + aggregate
    float* hc = h0;
    float* hn = h1;
    for (int l = 0; l < 2; l++) {
        k_node<<<(N_NODES * NCH) / 256, 256>>>(hc,
            tpw1 + l * 32 * 32, tpw2 + l * 16 * 32,
            tpw3 + l * 32 * 16, tpw4 + l * 16 * 16, V);
        k_agg<<<N_NODES, 64>>>(V, rowptr, csrc, coef, hn);
        float* t = hc; hc = hn; hn = t;
    }

    // layer 2 fused with readout
    k_node<<<(N_NODES * NCH) / 256, 256>>>(hc,
        tpw1 + 2 * 32 * 32, tpw2 + 2 * 16 * 32,
        tpw3 + 2 * 32 * 16, tpw4 + 2 * 16 * 16, V);
    k_agg_final<<<N_NODES, 64>>>(V, rowptr, csrc, coef, W_out, b_out, out);
}

// round 3
// speedup vs baseline: 1.3288x; 1.2838x over previous
#include <cuda_runtime.h>

#define N_NODES 65536
#define N_EDGES 1048576
#define HID 80
#define NCH 48   // 32 scalar channels + 16 vector channels, one float4 each
#define EDGE_CHUNK 64
#define NPB 16   // nodes per k_node block

// ---------------- static scratch (no allocations allowed) ----------------
__device__ float  g_h0[N_NODES * HID];
__device__ float  g_h1[N_NODES * HID];
__device__ float4 g_V[N_NODES * NCH];
__device__ int    g_deg[N_NODES];
__device__ int    g_rowptr[N_NODES + 1];
__device__ int    g_cursor[N_NODES];
__device__ int    g_csrc[N_EDGES];
__device__ float4 g_coef[N_EDGES];

// normalization constants (e3nn fan-in norms * 1/sqrt(2) * 1/sqrt(DEG=16))
#define K1C (0.03125f)
#define K2C (0.025515518f)
#define K3C (0.03125f)
#define K4C (0.044194174f)

// ---------------- preprocessing ----------------
__global__ void k_zero(int* __restrict__ deg) {
    int i = blockIdx.x * blockDim.x + threadIdx.x;
    if (i < N_NODES) deg[i] = 0;
}

__global__ void k_hist(const int* __restrict__ dst, int* __restrict__ deg) {
    int e = blockIdx.x * blockDim.x + threadIdx.x;
    if (e < N_EDGES) atomicAdd(&deg[dst[e]], 1);
}

// single-block exclusive scan over 65536 ints (256 threads x 256 elems)
__global__ void k_scan(const int* __restrict__ deg, int* __restrict__ rowptr,
                       int* __restrict__ cursor) {
    __shared__ int sums[256];
    int tid = threadIdx.x;
    int base = tid * 256;
    const int4* d4 = (const int4*)(deg + base);
    int s = 0;
#pragma unroll 8
    for (int i = 0; i < 64; i++) {
        int4 v = d4[i];
        s += v.x + v.y + v.z + v.w;
    }
    sums[tid] = s;
    __syncthreads();
    if (tid == 0) {
        int acc = 0;
        for (int i = 0; i < 256; i++) { int t = sums[i]; sums[i] = acc; acc += t; }
    }
    __syncthreads();
    int off = sums[tid];
    for (int i = 0; i < 256; i++) {
        rowptr[base + i] = off;
        cursor[base + i] = off;
        off += deg[base + i];
    }
    if (tid == 255) rowptr[N_NODES] = off;
}

__global__ void k_csr(const int* __restrict__ src, const int* __restrict__ dst,
                      const float4* __restrict__ eattr,
                      int* __restrict__ cursor, int* __restrict__ csrc,
                      float4* __restrict__ coef) {
    int e = blockIdx.x * blockDim.x + threadIdx.x;
    if (e >= N_EDGES) return;
    int d = dst[e];
    int pos = atomicAdd(&cursor[d], 1);
    csrc[pos] = src[e];
    coef[pos] = eattr[e];   // (s2, v2x, v2y, v2z)
}

// ---------------- input embed: h = x @ W_in + b_in ----------------
__global__ void k_input(const float* __restrict__ x, const float* __restrict__ W_in,
                        const float* __restrict__ b_in, float* __restrict__ h) {
    int id = blockIdx.x * blockDim.x + threadIdx.x;   // N*80
    if (id >= N_NODES * HID) return;
    int n = id / HID, c = id % HID;
    const float* xr = x + n * 16;
    float acc = b_in[c];
#pragma unroll
    for (int i = 0; i < 16; i++) acc = fmaf(xr[i], W_in[i * HID + c], acc);
    h[id] = acc;
}

// ---------------- per-node transform: register-blocked 2 nodes x 2 channels ----
// Block: 192 threads = 8 node-pairs x 24 channel-pair threads. 16 nodes/block.
__global__ __launch_bounds__(192) void k_node(
    const float* __restrict__ h,
    const float* __restrict__ w1, const float* __restrict__ w2,
    const float* __restrict__ w3, const float* __restrict__ w4,
    float4* __restrict__ V)
{
    __shared__ float s_w1[1024];   // 32x32
    __shared__ float s_w2[512];    // 16x32
    __shared__ float s_w3[512];    // 32x16
    __shared__ float s_w4[256];    // 16x16
    __shared__ float s_h[NPB][HID];
    int tid = threadIdx.x;
    for (int i = tid; i < 1024; i += 192) s_w1[i] = w1[i];
    for (int i = tid; i < 512;  i += 192) s_w2[i] = w2[i];
    for (int i = tid; i < 512;  i += 192) s_w3[i] = w3[i];
    for (int i = tid; i < 256;  i += 192) s_w4[i] = w4[i];
    int nb = blockIdx.x * NPB;
    {
        const float4* h4 = (const float4*)(h + nb * HID);  // 16*80/4 = 320 float4
        float4* sh4 = (float4*)&s_h[0][0];
        for (int i = tid; i < NPB * HID / 4; i += 192) sh4[i] = h4[i];
    }
    __syncthreads();

    int g  = tid / 24;   // node pair 0..7
    int cp = tid % 24;   // channel pair
    const float* hA = s_h[2 * g];
    const float* hB = s_h[2 * g + 1];
    float4* VA = V + (nb + 2 * g) * NCH;
    float4* VB = V + (nb + 2 * g + 1) * NCH;

    if (cp < 16) {
        // scalar channels c0, c1 in [0,32)
        int c0 = 2 * cp, c1 = c0 + 1;
        float pA0 = 0.f, pA1 = 0.f, pB0 = 0.f, pB1 = 0.f;
#pragma unroll
        for (int a = 0; a < 32; a++) {
            float xA = hA[a], xB = hB[a];
            float u = s_w1[a * 32 + c0], v = s_w1[a * 32 + c1];
            pA0 = fmaf(xA, u, pA0); pA1 = fmaf(xA, v, pA1);
            pB0 = fmaf(xB, u, pB0); pB1 = fmaf(xB, v, pB1);
        }
        float tA0x = 0.f, tA0y = 0.f, tA0z = 0.f;
        float tA1x = 0.f, tA1y = 0.f, tA1z = 0.f;
        float tB0x = 0.f, tB0y = 0.f, tB0z = 0.f;
        float tB1x = 0.f, tB1y = 0.f, tB1z = 0.f;
#pragma unroll
        for (int a = 0; a < 16; a++) {
            float u = s_w2[a * 32 + c0], v = s_w2[a * 32 + c1];
            float xA = hA[32 + a * 3], yA = hA[32 + a * 3 + 1], zA = hA[32 + a * 3 + 2];
            float xB = hB[32 + a * 3], yB = hB[32 + a * 3 + 1], zB = hB[32 + a * 3 + 2];
            tA0x = fmaf(xA, u, tA0x); tA0y = fmaf(yA, u, tA0y); tA0z = fmaf(zA, u, tA0z);
            tA1x = fmaf(xA, v, tA1x); tA1y = fmaf(yA, v, tA1y); tA1z = fmaf(zA, v, tA1z);
            tB0x = fmaf(xB, u, tB0x); tB0y = fmaf(yB, u, tB0y); tB0z = fmaf(zB, u, tB0z);
            tB1x = fmaf(xB, v, tB1x); tB1y = fmaf(yB, v, tB1y); tB1z = fmaf(zB, v, tB1z);
        }
        VA[c0] = make_float4(K1C * pA0, K2C * tA0x, K2C * tA0y, K2C * tA0z);
        VA[c1] = make_float4(K1C * pA1, K2C * tA1x, K2C * tA1y, K2C * tA1z);
        VB[c0] = make_float4(K1C * pB0, K2C * tB0x, K2C * tB0y, K2C * tB0z);
        VB[c1] = make_float4(K1C * pB1, K2C * tB1x, K2C * tB1y, K2C * tB1z);
    } else {
        // vector channels c0, c1 in [0,16), stored at NCH offset 32+c
        int c0 = (cp - 16) * 2, c1 = c0 + 1;
        float pA0 = 0.f, pA1 = 0.f, pB0 = 0.f, pB1 = 0.f;
#pragma unroll
        for (int a = 0; a < 32; a++) {
            float xA = hA[a], xB = hB[a];
            float u = s_w3[a * 16 + c0], v = s_w3[a * 16 + c1];
            pA0 = fmaf(xA, u, pA0); pA1 = fmaf(xA, v, pA1);
            pB0 = fmaf(xB, u, pB0); pB1 = fmaf(xB, v, pB1);
        }
        float tA0x = 0.f, tA0y = 0.f, tA0z = 0.f;
        float tA1x = 0.f, tA1y = 0.f, tA1z = 0.f;
        float tB0x = 0.f, tB0y = 0.f, tB0z = 0.f;
        float tB1x = 0.f, tB1y = 0.f, tB1z = 0.f;
#pragma unroll
        for (int a = 0; a < 16; a++) {
            float u = s_w4[a * 16 + c0], v = s_w4[a * 16 + c1];
            float xA = hA[32 + a * 3], yA = hA[32 + a * 3 + 1], zA = hA[32 + a * 3 + 2];
            float xB = hB[32 + a * 3], yB = hB[32 + a * 3 + 1], zB = hB[32 + a * 3 + 2];
            tA0x = fmaf(xA, u, tA0x); tA0y = fmaf(yA, u, tA0y); tA0z = fmaf(zA, u, tA0z);
            tA1x = fmaf(xA, v, tA1x); tA1y = fmaf(yA, v, tA1y); tA1z = fmaf(zA, v, tA1z);
            tB0x = fmaf(xB, u, tB0x); tB0y = fmaf(yB, u, tB0y); tB0z = fmaf(zB, u, tB0z);
            tB1x = fmaf(xB, v, tB1x); tB1y = fmaf(yB, v, tB1y); tB1z = fmaf(zB, v, tB1z);
        }
        VA[32 + c0] = make_float4(K3C * pA0, K4C * tA0x, K4C * tA0y, K4C * tA0z);
        VA[32 + c1] = make_float4(K3C * pA1, K4C * tA1x, K4C * tA1y, K4C * tA1z);
        VB[32 + c0] = make_float4(K3C * pB0, K4C * tB0x, K4C * tB0y, K4C * tB0z);
        VB[32 + c1] = make_float4(K3C * pB1, K4C * tB1x, K4C * tB1y, K4C * tB1z);
    }
}

// ---------------- aggregation: one block (64 threads) per dst node ----------------
__device__ __forceinline__ void agg_node(
    const float4* __restrict__ V, const int* __restrict__ rowptr,
    const int* __restrict__ csrc, const float4* __restrict__ coef,
    int n, int tid, int* s_src, float4* s_cf,
    float& a0, float& a1, float& a2)
{
    int beg = rowptr[n], end = rowptr[n + 1];
    int ch = tid;
    bool is_s = (ch < 32);
    a0 = a1 = a2 = 0.f;
    for (int base = beg; base < end; base += EDGE_CHUNK) {
        int cnt = min(EDGE_CHUNK, end - base);
        __syncthreads();
        if (tid < cnt) {
            s_src[tid] = csrc[base + tid];
            s_cf[tid]  = coef[base + tid];
        }
        __syncthreads();
        if (ch < NCH) {
#pragma unroll 4
            for (int i = 0; i < cnt; i++) {
                int s = s_src[i];
                float4 cf = s_cf[i];
                float4 v = V[s * NCH + ch];
                if (is_s) {
                    a0 = fmaf(cf.x, v.x, a0);
                    a0 = fmaf(cf.y, v.y, a0);
                    a0 = fmaf(cf.z, v.z, a0);
                    a0 = fmaf(cf.w, v.w, a0);
                } else {
                    a0 = fmaf(cf.y, v.x, fmaf(cf.x, v.y, a0));
                    a1 = fmaf(cf.z, v.x, fmaf(cf.x, v.z, a1));
                    a2 = fmaf(cf.w, v.x, fmaf(cf.x, v.w, a2));
                }
            }
        }
    }
}

__global__ __launch_bounds__(64) void k_agg(
    const float4* __restrict__ V, const int* __restrict__ rowptr,
    const int* __restrict__ csrc, const float4* __restrict__ coef,
    float* __restrict__ hout)
{
    __shared__ int    s_src[EDGE_CHUNK];
    __shared__ float4 s_cf[EDGE_CHUNK];
    int n = blockIdx.x;
    int tid = threadIdx.x;
    float a0, a1, a2;
    agg_node(V, rowptr, csrc, coef, n, tid, s_src, s_cf, a0, a1, a2);
    if (tid < 32) {
        hout[n * HID + tid] = a0;
    } else if (tid < NCH) {
        int b = n * HID + 32 + (tid - 32) * 3;
        hout[b + 0] = a0;
        hout[b + 1] = a1;
        hout[b + 2] = a2;
    }
}

// last layer: fuse ReLU + W_out readout
__global__ __launch_bounds__(64) void k_agg_final(
    const float4* __restrict__ V, const int* __restrict__ rowptr,
    const int* __restrict__ csrc, const float4* __restrict__ coef,
    const float* __restrict__ W_out, const float* __restrict__ b_out,
    float* __restrict__ out)
{
    __shared__ int    s_src[EDGE_CHUNK];
    __shared__ float4 s_cf[EDGE_CHUNK];
    __shared__ float  sh[HID];
    int n = blockIdx.x;
    int tid = threadIdx.x;
    float a0, a1, a2;
    agg_node(V, rowptr, csrc, coef, n, tid, s_src, s_cf, a0, a1, a2);
    __syncthreads();
    if (tid < 32) {
        sh[tid] = fmaxf(a0, 0.f);
    } else if (tid < NCH) {
        int b = 32 + (tid - 32) * 3;
        sh[b + 0] = fmaxf(a0, 0.f);
        sh[b + 1] = fmaxf(a1, 0.f);
        sh[b + 2] = fmaxf(a2, 0.f);
    }
    __syncthreads();
    if (tid < 8) {
        float acc = b_out[tid];
#pragma unroll
        for (int c = 0; c < HID; c++)
            acc = fmaf(sh[c], W_out[c * 8 + tid], acc);
        out[n * 8 + tid] = acc;
    }
}

// ---------------- launch ----------------
extern "C" void kernel_launch(void* const* d_in, const int* in_sizes, int n_in,
                              void* d_out, int out_size) {
    const float* x     = (const float*)d_in[0];
    const int*   eidx  = (const int*)d_in[1];     // (2, E) int32: row0=src, row1=dst
    const float* eattr = (const float*)d_in[2];   // (E, 4)
    const float* W_in  = (const float*)d_in[3];
    const float* b_in  = (const float*)d_in[4];
    const float* tpw1  = (const float*)d_in[5];   // (3,32,32)
    const float* tpw2  = (const float*)d_in[6];   // (3,16,32)
    const float* tpw3  = (const float*)d_in[7];   // (3,32,16)
    const float* tpw4  = (const float*)d_in[8];   // (3,16,16)
    const float* W_out = (const float*)d_in[9];
    const float* b_out = (const float*)d_in[10];
    float* out = (float*)d_out;

    float *h0, *h1; float4 *V, *coef; int *deg, *rowptr, *cursor, *csrc;
    cudaGetSymbolAddress((void**)&h0,     g_h0);
    cudaGetSymbolAddress((void**)&h1,     g_h1);
    cudaGetSymbolAddress((void**)&V,      g_V);
    cudaGetSymbolAddress((void**)&deg,    g_deg);
    cudaGetSymbolAddress((void**)&rowptr, g_rowptr);
    cudaGetSymbolAddress((void**)&cursor, g_cursor);
    cudaGetSymbolAddress((void**)&csrc,   g_csrc);
    cudaGetSymbolAddress((void**)&coef,   g_coef);

    const int* src = eidx;
    const int* dst = eidx + N_EDGES;

    // CSR build
    k_zero<<<N_NODES / 256, 256>>>(deg);
    k_hist<<<N_EDGES / 256, 256>>>(dst, deg);
    k_scan<<<1, 256>>>(deg, rowptr, cursor);
    k_csr<<<N_EDGES / 256, 256>>>(src, dst, (const float4*)eattr, cursor, csrc, coef);

    // input embed
    k_input<<<(N_NODES * HID) / 256, 256>>>(x, W_in, b_in, h0);

    // layers 0,1: node transform + aggregate
    float* hc = h0;
    float* hn = h1;
    for (int l = 0; l < 2; l++) {
        k_node<<<N_NODES / NPB, 192>>>(hc,
            tpw1 + l * 32 * 32, tpw2 + l * 16 * 32,
            tpw3 + l * 32 * 16, tpw4 + l * 16 * 16, V);
        k_agg<<<N_NODES, 64>>>(V, rowptr, csrc, coef, hn);
        float* t = hc; hc = hn; hn = t;
    }

    // layer 2 fused with readout
    k_node<<<N_NODES / NPB, 192>>>(hc,
        tpw1 + 2 * 32 * 32, tpw2 + 2 * 16 * 32,
        tpw3 + 2 * 32 * 16, tpw4 + 2 * 16 * 16, V);
    k_agg_final<<<N_NODES, 64>>>(V, rowptr, csrc, coef, W_out, b_out, out);
}

// round 4
// speedup vs baseline: 1.4409x; 1.0844x over previous
#include <cuda_runtime.h>
#include <cuda_fp16.h>

#define N_NODES 65536
#define N_EDGES 1048576
#define HID 80
#define NCH 48   // 32 scalar channels + 16 vector channels
#define EDGE_CHUNK 64
#define NPB 16   // nodes per k_node block

// ---------------- static scratch (no allocations allowed) ----------------
__device__ float  g_h0[N_NODES * HID];
__device__ float  g_h1[N_NODES * HID];
__device__ uint2  g_V[N_NODES * NCH];        // 4 x fp16 per channel (25 MB)
__device__ int    g_deg[N_NODES];
__device__ int    g_rowptr[N_NODES + 1];
__device__ int    g_cursor[N_NODES];
__device__ int    g_csrc[N_EDGES];
__device__ float4 g_coef[N_EDGES];

// normalization constants (e3nn fan-in norms * 1/sqrt(2) * 1/sqrt(DEG=16))
#define K1C (0.03125f)
#define K2C (0.025515518f)
#define K3C (0.03125f)
#define K4C (0.044194174f)

__device__ __forceinline__ uint2 pack4h(float a, float b, float c, float d) {
    __half2 lo = __floats2half2_rn(a, b);
    __half2 hi = __floats2half2_rn(c, d);
    uint2 r;
    r.x = *(const unsigned int*)&lo;
    r.y = *(const unsigned int*)&hi;
    return r;
}

// ---------------- preprocessing ----------------
__global__ void k_zero(int* __restrict__ deg) {
    int i = blockIdx.x * blockDim.x + threadIdx.x;
    if (i < N_NODES) deg[i] = 0;
}

__global__ void k_hist(const int* __restrict__ dst, int* __restrict__ deg) {
    int e = blockIdx.x * blockDim.x + threadIdx.x;
    if (e < N_EDGES) atomicAdd(&deg[dst[e]], 1);
}

// single-block (1024 threads) exclusive scan over 65536 ints; each thread owns 64
__global__ __launch_bounds__(1024) void k_scan(
    const int* __restrict__ deg, int* __restrict__ rowptr, int* __restrict__ cursor)
{
    __shared__ int wsum[32];
    int tid = threadIdx.x;
    int lane = tid & 31, wid = tid >> 5;
    int base = tid * 64;
    const int4* d4 = (const int4*)(deg + base);
    int s = 0;
#pragma unroll
    for (int i = 0; i < 16; i++) {
        int4 v = d4[i];
        s += v.x + v.y + v.z + v.w;
    }
    // inclusive warp scan of s
    int v = s;
#pragma unroll
    for (int d = 1; d < 32; d <<= 1) {
        int t = __shfl_up_sync(0xffffffffu, v, d);
        if (lane >= d) v += t;
    }
    if (lane == 31) wsum[wid] = v;
    __syncthreads();
    if (wid == 0) {
        int w = wsum[lane];
        int wv = w;
#pragma unroll
        for (int d = 1; d < 32; d <<= 1) {
            int t = __shfl_up_sync(0xffffffffu, wv, d);
            if (lane >= d) wv += t;
        }
        wsum[lane] = wv - w;   // exclusive warp offsets
    }
    __syncthreads();
    int off = wsum[wid] + (v - s);   // exclusive prefix for this thread
#pragma unroll
    for (int i = 0; i < 16; i++) {
        int4 dv = d4[i];
        int b = base + i * 4;
        rowptr[b + 0] = off; cursor[b + 0] = off; off += dv.x;
        rowptr[b + 1] = off; cursor[b + 1] = off; off += dv.y;
        rowptr[b + 2] = off; cursor[b + 2] = off; off += dv.z;
        rowptr[b + 3] = off; cursor[b + 3] = off; off += dv.w;
    }
    if (tid == 1023) rowptr[N_NODES] = off;
}

__global__ void k_csr(const int* __restrict__ src, const int* __restrict__ dst,
                      const float4* __restrict__ eattr,
                      int* __restrict__ cursor, int* __restrict__ csrc,
                      float4* __restrict__ coef) {
    int e = blockIdx.x * blockDim.x + threadIdx.x;
    if (e >= N_EDGES) return;
    int d = dst[e];
    int pos = atomicAdd(&cursor[d], 1);
    csrc[pos] = src[e];
    coef[pos] = eattr[e];   // (s2, v2x, v2y, v2z)
}

// ---------------- input embed: h = x @ W_in + b_in ----------------
__global__ void k_input(const float* __restrict__ x, const float* __restrict__ W_in,
                        const float* __restrict__ b_in, float* __restrict__ h) {
    int id = blockIdx.x * blockDim.x + threadIdx.x;   // N*80
    if (id >= N_NODES * HID) return;
    int n = id / HID, c = id % HID;
    const float* xr = x + n * 16;
    float acc = b_in[c];
#pragma unroll
    for (int i = 0; i < 16; i++) acc = fmaf(xr[i], W_in[i * HID + c], acc);
    h[id] = acc;
}

// ---------------- per-node transform: register-blocked 2 nodes x 2 channels ----
__global__ __launch_bounds__(192) void k_node(
    const float* __restrict__ h,
    const float* __restrict__ w1, const float* __restrict__ w2,
    const float* __restrict__ w3, const float* __restrict__ w4,
    uint2* __restrict__ V)
{
    __shared__ float s_w1[1024];   // 32x32
    __shared__ float s_w2[512];    // 16x32
    __shared__ float s_w3[512];    // 32x16
    __shared__ float s_w4[256];    // 16x16
    __shared__ float s_h[NPB][HID];
    int tid = threadIdx.x;
    for (int i = tid; i < 1024; i += 192) s_w1[i] = w1[i];
    for (int i = tid; i < 512;  i += 192) s_w2[i] = w2[i];
    for (int i = tid; i < 512;  i += 192) s_w3[i] = w3[i];
    for (int i = tid; i < 256;  i += 192) s_w4[i] = w4[i];
    int nb = blockIdx.x * NPB;
    {
        const float4* h4 = (const float4*)(h + nb * HID);
        float4* sh4 = (float4*)&s_h[0][0];
        for (int i = tid; i < NPB * HID / 4; i += 192) sh4[i] = h4[i];
    }
    __syncthreads();

    int g  = tid / 24;   // node pair 0..7
    int cp = tid % 24;   // channel pair
    const float* hA = s_h[2 * g];
    const float* hB = s_h[2 * g + 1];
    uint2* VA = V + (nb + 2 * g) * NCH;
    uint2* VB = V + (nb + 2 * g + 1) * NCH;

    if (cp < 16) {
        int c0 = 2 * cp, c1 = c0 + 1;
        float pA0 = 0.f, pA1 = 0.f, pB0 = 0.f, pB1 = 0.f;
#pragma unroll
        for (int a = 0; a < 32; a++) {
            float xA = hA[a], xB = hB[a];
            float u = s_w1[a * 32 + c0], v = s_w1[a * 32 + c1];
            pA0 = fmaf(xA, u, pA0); pA1 = fmaf(xA, v, pA1);
            pB0 = fmaf(xB, u, pB0); pB1 = fmaf(xB, v, pB1);
        }
        float tA0x = 0.f, tA0y = 0.f, tA0z = 0.f;
        float tA1x = 0.f, tA1y = 0.f, tA1z = 0.f;
        float tB0x = 0.f, tB0y = 0.f, tB0z = 0.f;
        float tB1x = 0.f, tB1y = 0.f, tB1z = 0.f;
#pragma unroll
        for (int a = 0; a < 16; a++) {
            float u = s_w2[a * 32 + c0], v = s_w2[a * 32 + c1];
            float xA = hA[32 + a * 3], yA = hA[32 + a * 3 + 1], zA = hA[32 + a * 3 + 2];
            float xB = hB[32 + a * 3], yB = hB[32 + a * 3 + 1], zB = hB[32 + a * 3 + 2];
            tA0x = fmaf(xA, u, tA0x); tA0y = fmaf(yA, u, tA0y); tA0z = fmaf(zA, u, tA0z);
            tA1x = fmaf(xA, v, tA1x); tA1y = fmaf(yA, v, tA1y); tA1z = fmaf(zA, v, tA1z);
            tB0x = fmaf(xB, u, tB0x); tB0y = fmaf(yB, u, tB0y); tB0z = fmaf(zB, u, tB0z);
            tB1x = fmaf(xB, v, tB1x); tB1y = fmaf(yB, v, tB1y); tB1z = fmaf(zB, v, tB1z);
        }
        VA[c0] = pack4h(K1C * pA0, K2C * tA0x, K2C * tA0y, K2C * tA0z);
        VA[c1] = pack4h(K1C * pA1, K2C * tA1x, K2C * tA1y, K2C * tA1z);
        VB[c0] = pack4h(K1C * pB0, K2C * tB0x, K2C * tB0y, K2C * tB0z);
        VB[c1] = pack4h(K1C * pB1, K2C * tB1x, K2C * tB1y, K2C * tB1z);
    } else {
        int c0 = (cp - 16) * 2, c1 = c0 + 1;
        float pA0 = 0.f, pA1 = 0.f, pB0 = 0.f, pB1 = 0.f;
#pragma unroll
        for (int a = 0; a < 32; a++) {
            float xA = hA[a], xB = hB[a];
            float u = s_w3[a * 16 + c0], v = s_w3[a * 16 + c1];
            pA0 = fmaf(xA, u, pA0); pA1 = fmaf(xA, v, pA1);
            pB0 = fmaf(xB, u, pB0); pB1 = fmaf(xB, v, pB1);
        }
        float tA0x = 0.f, tA0y = 0.f, tA0z = 0.f;
        float tA1x = 0.f, tA1y = 0.f, tA1z = 0.f;
        float tB0x = 0.f, tB0y = 0.f, tB0z = 0.f;
        float tB1x = 0.f, tB1y = 0.f, tB1z = 0.f;
#pragma unroll
        for (int a = 0; a < 16; a++) {
            float u = s_w4[a * 16 + c0], v = s_w4[a * 16 + c1];
            float xA = hA[32 + a * 3], yA = hA[32 + a * 3 + 1], zA = hA[32 + a * 3 + 2];
            float xB = hB[32 + a * 3], yB = hB[32 + a * 3 + 1], zB = hB[32 + a * 3 + 2];
            tA0x = fmaf(xA, u, tA0x); tA0y = fmaf(yA, u, tA0y); tA0z = fmaf(zA, u, tA0z);
            tA1x = fmaf(xA, v, tA1x); tA1y = fmaf(yA, v, tA1y); tA1z = fmaf(zA, v, tA1z);
            tB0x = fmaf(xB, u, tB0x); tB0y = fmaf(yB, u, tB0y); tB0z = fmaf(zB, u, tB0z);
            tB1x = fmaf(xB, v, tB1x); tB1y = fmaf(yB, v, tB1y); tB1z = fmaf(zB, v, tB1z);
        }
        VA[32 + c0] = pack4h(K3C * pA0, K4C * tA0x, K4C * tA0y, K4C * tA0z);
        VA[32 + c1] = pack4h(K3C * pA1, K4C * tA1x, K4C * tA1y, K4C * tA1z);
        VB[32 + c0] = pack4h(K3C * pB0, K4C * tB0x, K4C * tB0y, K4C * tB0z);
        VB[32 + c1] = pack4h(K3C * pB1, K4C * tB1x, K4C * tB1y, K4C * tB1z);
    }
}

// ---------------- aggregation: one block (64 threads) per dst node ----------------
__device__ __forceinline__ void agg_node(
    const uint2* __restrict__ V, const int* __restrict__ rowptr,
    const int* __restrict__ csrc, const float4* __restrict__ coef,
    int n, int tid, int* s_src, float4* s_cf,
    float& a0, float& a1, float& a2)
{
    int beg = rowptr[n], end = rowptr[n + 1];
    int ch = tid;
    bool is_s = (ch < 32);
    a0 = a1 = a2 = 0.f;
    for (int base = beg; base < end; base += EDGE_CHUNK) {
        int cnt = min(EDGE_CHUNK, end - base);
        __syncthreads();
        if (tid < cnt) {
            s_src[tid] = csrc[base + tid];
            s_cf[tid]  = coef[base + tid];
        }
        __syncthreads();
        if (ch < NCH) {
#pragma unroll 4
            for (int i = 0; i < cnt; i++) {
                int s = s_src[i];
                float4 cf = s_cf[i];
                uint2 vp = V[s * NCH + ch];
                float2 f0 = __half22float2(*(const __half2*)&vp.x);  // (P, t.x)
                float2 f1 = __half22float2(*(const __half2*)&vp.y);  // (t.y, t.z)
                if (is_s) {
                    a0 = fmaf(cf.x, f0.x, a0);
                    a0 = fmaf(cf.y, f0.y, a0);
                    a0 = fmaf(cf.z, f1.x, a0);
                    a0 = fmaf(cf.w, f1.y, a0);
                } else {
                    a0 = fmaf(cf.y, f0.x, fmaf(cf.x, f0.y, a0));
                    a1 = fmaf(cf.z, f0.x, fmaf(cf.x, f1.x, a1));
                    a2 = fmaf(cf.w, f0.x, fmaf(cf.x, f1.y, a2));
                }
            }
        }
    }
}

__global__ __launch_bounds__(64) void k_agg(
    const uint2* __restrict__ V, const int* __restrict__ rowptr,
    const int* __restrict__ csrc, const float4* __restrict__ coef,
    float* __restrict__ hout)
{
    __shared__ int    s_src[EDGE_CHUNK];
    __shared__ float4 s_cf[EDGE_CHUNK];
    int n = blockIdx.x;
    int tid = threadIdx.x;
    float a0, a1, a2;
    agg_node(V, rowptr, csrc, coef, n, tid, s_src, s_cf, a0, a1, a2);
    if (tid < 32) {
        hout[n * HID + tid] = a0;
    } else if (tid < NCH) {
        int b = n * HID + 32 + (tid - 32) * 3;
        hout[b + 0] = a0;
        hout[b + 1] = a1;
        hout[b + 2] = a2;
    }
}

// last layer: fuse ReLU + W_out readout
__global__ __launch_bounds__(64) void k_agg_final(
    const uint2* __restrict__ V, const int* __restrict__ rowptr,
    const int* __restrict__ csrc, const float4* __restrict__ coef,
    const float* __restrict__ W_out, const float* __restrict__ b_out,
    float* __restrict__ out)
{
    __shared__ int    s_src[EDGE_CHUNK];
    __shared__ float4 s_cf[EDGE_CHUNK];
    __shared__ float  sh[HID];
    int n = blockIdx.x;
    int tid = threadIdx.x;
    float a0, a1, a2;
    agg_node(V, rowptr, csrc, coef, n, tid, s_src, s_cf, a0, a1, a2);
    __syncthreads();
    if (tid < 32) {
        sh[tid] = fmaxf(a0, 0.f);
    } else if (tid < NCH) {
        int b = 32 + (tid - 32) * 3;
        sh[b + 0] = fmaxf(a0, 0.f);
        sh[b + 1] = fmaxf(a1, 0.f);
        sh[b + 2] = fmaxf(a2, 0.f);
    }
    __syncthreads();
    if (tid < 8) {
        float acc = b_out[tid];
#pragma unroll
        for (int c = 0; c < HID; c++)
            acc = fmaf(sh[c], W_out[c * 8 + tid], acc);
        out[n * 8 + tid] = acc;
    }
}

// ---------------- launch ----------------
extern "C" void kernel_launch(void* const* d_in, const int* in_sizes, int n_in,
                              void* d_out, int out_size) {
    const float* x     = (const float*)d_in[0];
    const int*   eidx  = (const int*)d_in[1];     // (2, E) int32: row0=src, row1=dst
    const float* eattr = (const float*)d_in[2];   // (E, 4)
    const float* W_in  = (const float*)d_in[3];
    const float* b_in  = (const float*)d_in[4];
    const float* tpw1  = (const float*)d_in[5];   // (3,32,32)
    const float* tpw2  = (const float*)d_in[6];   // (3,16,32)
    const float* tpw3  = (const float*)d_in[7];   // (3,32,16)
    const float* tpw4  = (const float*)d_in[8];   // (3,16,16)
    const float* W_out = (const float*)d_in[9];
    const float* b_out = (const float*)d_in[10];
    float* out = (float*)d_out;

    float *h0, *h1; uint2 *V; float4 *coef; int *deg, *rowptr, *cursor, *csrc;
    cudaGetSymbolAddress((void**)&h0,     g_h0);
    cudaGetSymbolAddress((void**)&h1,     g_h1);
    cudaGetSymbolAddress((void**)&V,      g_V);
    cudaGetSymbolAddress((void**)&deg,    g_deg);
    cudaGetSymbolAddress((void**)&rowptr, g_rowptr);
    cudaGetSymbolAddress((void**)&cursor, g_cursor);
    cudaGetSymbolAddress((void**)&csrc,   g_csrc);
    cudaGetSymbolAddress((void**)&coef,   g_coef);

    const int* src = eidx;
    const int* dst = eidx + N_EDGES;

    // CSR build
    k_zero<<<N_NODES / 256, 256>>>(deg);
    k_hist<<<N_EDGES / 256, 256>>>(dst, deg);
    k_scan<<<1, 1024>>>(deg, rowptr, cursor);
    k_csr<<<N_EDGES / 256, 256>>>(src, dst, (const float4*)eattr, cursor, csrc, coef);

    // input embed
    k_input<<<(N_NODES * HID) / 256, 256>>>(x, W_in, b_in, h0);

    // layers 0,1: node transform + aggregate
    float* hc = h0;
    float* hn = h1;
    for (int l = 0; l < 2; l++) {
        k_node<<<N_NODES / NPB, 192>>>(hc,
            tpw1 + l * 32 * 32, tpw2 + l * 16 * 32,
            tpw3 + l * 32 * 16, tpw4 + l * 16 * 16, V);
        k_agg<<<N_NODES, 64>>>(V, rowptr, csrc, coef, hn);
        float* t = hc; hc = hn; hn = t;
    }

    // layer 2 fused with readout
    k_node<<<N_NODES / NPB, 192>>>(hc,
        tpw1 + 2 * 32 * 32, tpw2 + 2 * 16 * 32,
        tpw3 + 2 * 32 * 16, tpw4 + 2 * 16 * 16, V);
    k_agg_final<<<N_NODES, 64>>>(V, rowptr, csrc, coef, W_out, b_out, out);
}